// round 13
// baseline (speedup 1.0000x reference)
#include <cuda_runtime.h>

#define BB 4096
#define TT 512
#define HH 32
#define NB 4

typedef unsigned long long u64;

__device__ __forceinline__ u64 pk2(float lo, float hi) {
    u64 r; asm("mov.b64 %0, {%1,%2};" : "=l"(r) : "f"(lo), "f"(hi)); return r;
}
__device__ __forceinline__ void unpk2(u64 v, float& a, float& b) {
    asm("mov.b64 {%0,%1}, %2;" : "=f"(a), "=f"(b) : "l"(v));
}
__device__ __forceinline__ u64 ffma2(u64 a, u64 b, u64 c) {
    u64 d; asm("fma.rn.f32x2 %0, %1, %2, %3;" : "=l"(d) : "l"(a), "l"(b), "l"(c));
    return d;
}
__device__ __forceinline__ u64 fadd2(u64 a, u64 b) {
    u64 d; asm("add.rn.f32x2 %0, %1, %2;" : "=l"(d) : "l"(a), "l"(b));
    return d;
}

// tanh with 2*log2(e) pre-folded: tanh(v) = 1 - 2*rcp(ex2(v') + 1)
__device__ __forceinline__ float tanh_scaled(float vp) {
    float e; asm("ex2.approx.f32 %0, %1;" : "=f"(e) : "f"(vp));
    float r; asm("rcp.approx.f32 %0, %1;" : "=f"(r) : "f"(e + 1.0f));
    return fmaf(-2.0f, r, 1.0f);
}

__device__ __forceinline__ float hsum2(u64 v) {
    float lo, hi; unpk2(v, lo, hi); return lo + hi;
}

__global__ void __launch_bounds__(64, 8)
rnn2_kernel(const float* __restrict__ x,       // [B, T, 1]
            const float* __restrict__ hstate,  // [2, B, H]
            const float* __restrict__ Wih0,    // [H, 1]
            const float* __restrict__ Whh0,    // [H, H]
            const float* __restrict__ bih0, const float* __restrict__ bhh0,
            const float* __restrict__ Wih1,    // [H, H]
            const float* __restrict__ Whh1,    // [H, H]
            const float* __restrict__ bih1, const float* __restrict__ bhh1,
            const float* __restrict__ Wfc,     // [1, H]
            const float* __restrict__ bfc,     // [1]
            float* __restrict__ out)           // [B] pred ++ [2,B,H] h_new
{
    // Double-buffered h vectors per batch; one __syncthreads per phase.
    __shared__ __align__(16) float sh0[NB][2][HH];
    __shared__ __align__(16) float sh1[NB][2][HH];

    const int tid  = threadIdx.x;
    const int lane = tid & 31;
    const int w    = tid >> 5;
    const int n    = (w << 4) | (lane & 15);  // neuron 0..31
    const int kh   = lane >> 4;               // k-half 0/1
    const int koff = kh << 4;                 // element offset into h
    const int b0   = blockIdx.x * NB;

    const float SC = 2.885390081777927f;      // 2*log2(e), folded into weights

    // 16-wide k-slices of weight row n: 24 u64 = 48 regs
    u64 w0h[8], wi1h[8], wh1h[8];
    {
        const float2* p = (const float2*)(Whh0 + n * HH + koff);
        #pragma unroll
        for (int i = 0; i < 8; i++) { float2 f = p[i]; w0h[i]  = pk2(f.x*SC, f.y*SC); }
        p = (const float2*)(Wih1 + n * HH + koff);
        #pragma unroll
        for (int i = 0; i < 8; i++) { float2 f = p[i]; wi1h[i] = pk2(f.x*SC, f.y*SC); }
        p = (const float2*)(Whh1 + n * HH + koff);
        #pragma unroll
        for (int i = 0; i < 8; i++) { float2 f = p[i]; wh1h[i] = pk2(f.x*SC, f.y*SC); }
    }
    const float wx0 = Wih0[n] * SC;
    const float bb0 = (bih0[n] + bhh0[n]) * SC;
    const float bb1 = (bih1[n] + bhh1[n]) * SC;

    // init hidden state (buf 0)
    #pragma unroll
    for (int bi = 0; bi < NB; bi++) {
        if (kh == 0) sh0[bi][0][n] = hstate[(size_t)(b0 + bi) * HH + n];
        else         sh1[bi][0][n] = hstate[(size_t)BB * HH + (size_t)(b0 + bi) * HH + n];
    }
    __syncthreads();

    const float* xb = x + (size_t)b0 * TT;
    float xv[NB];

    // ---- prologue: L0(0) -> sh0[..][1] ----
    #pragma unroll
    for (int bi = 0; bi < NB; bi++) {
        u64 a = (kh == 0) ? pk2(fmaf(wx0, xb[bi * TT], bb0), 0.f) : pk2(0.f, 0.f);
        const ulonglong2* h0p = (const ulonglong2*)(&sh0[bi][0][koff]);
        #pragma unroll
        for (int i = 0; i < 4; i++) {
            ulonglong2 v = h0p[i];
            a = ffma2(w0h[2*i],     v.x, a);
            a = ffma2(w0h[2*i + 1], v.y, a);
        }
        float p0 = hsum2(a);
        float q0 = __shfl_xor_sync(0xffffffffu, p0, 16);
        if (kh == 0) sh0[bi][1][n] = tanh_scaled(p0 + q0);
        xv[bi] = xb[bi * TT + 1];
    }
    __syncthreads();

    // One phase: reads sh0[rb0]=h0'(te), sh1[rb1]=h1'(te-1);
    // writes sh0[wb0]=h0'(te+1) (kh=0 lanes), sh1[wb1]=h1'(te) (kh=1 lanes).
#define PHASE(s_, withL0, tn_)                                                 \
    {                                                                          \
        const int rb0 = (s_) ^ 1, wb0 = (s_), rb1 = (s_), wb1 = (s_) ^ 1;      \
        _Pragma("unroll")                                                      \
        for (int bi = 0; bi < NB; bi++) {                                      \
            u64 aL0 = (kh == 0) ? pk2(fmaf(wx0, xv[bi], bb0), 0.f)             \
                                : pk2(0.f, 0.f);                               \
            u64 aA  = (kh == 0) ? pk2(bb1, 0.f) : pk2(0.f, 0.f);               \
            u64 aB  = pk2(0.f, 0.f);                                           \
            if ((tn_) >= 0) xv[bi] = xb[bi * TT + (tn_)];                      \
            const ulonglong2* h0p = (const ulonglong2*)(&sh0[bi][rb0][koff]);  \
            const ulonglong2* h1p = (const ulonglong2*)(&sh1[bi][rb1][koff]);  \
            _Pragma("unroll")                                                  \
            for (int i = 0; i < 4; i++) {                                      \
                ulonglong2 v = h0p[i];                                         \
                if (withL0) {                                                  \
                    aL0 = ffma2(w0h[2*i],     v.x, aL0);                       \
                    aL0 = ffma2(w0h[2*i + 1], v.y, aL0);                       \
                }                                                              \
                aA = ffma2(wi1h[2*i],     v.x, aA);                            \
                aA = ffma2(wi1h[2*i + 1], v.y, aA);                            \
            }                                                                  \
            _Pragma("unroll")                                                  \
            for (int i = 0; i < 4; i++) {                                      \
                ulonglong2 u = h1p[i];                                         \
                aB = ffma2(wh1h[2*i],     u.x, aB);                            \
                aB = ffma2(wh1h[2*i + 1], u.y, aB);                            \
            }                                                                  \
            float p0 = (withL0) ? hsum2(aL0) : 0.f;                            \
            float p1 = hsum2(fadd2(aA, aB));                                   \
            float q0 = __shfl_xor_sync(0xffffffffu, p0, 16);                   \
            float q1 = __shfl_xor_sync(0xffffffffu, p1, 16);                   \
            float hv = tanh_scaled(kh ? (p1 + q1) : (p0 + q0));                \
            float* dst = kh ? &sh1[bi][wb1][n] : &sh0[bi][wb0][n];             \
            if (withL0 || kh) *dst = hv;                                       \
        }                                                                      \
    }

    // mainloop: te = 0..509 (paired), then te=510, then L1-only te=511
    #pragma unroll 1
    for (int t = 0; t < TT - 2; t += 2) {
        PHASE(0, true, t + 2);
        __syncthreads();
        PHASE(1, true, t + 3);
        __syncthreads();
    }
    PHASE(0, true, -1);       // te = 510: consumes x[511]
    __syncthreads();
    PHASE(1, false, -1);      // te = 511: L1 only; sh0 preserved (guarded)
    __syncthreads();

    // ---- outputs ----
    // h0'(TT-1) in sh0[bi][0], h1'(TT-1) in sh1[bi][0]
    if (w == 0) {
        #pragma unroll
        for (int bi = 0; bi < NB; bi++) {
            out[BB + (size_t)(b0 + bi) * HH + lane] = sh0[bi][0][lane];
            float p = Wfc[lane] * sh1[bi][0][lane];
            #pragma unroll
            for (int off = 16; off; off >>= 1)
                p += __shfl_xor_sync(0xffffffffu, p, off);
            if (lane == 0) out[b0 + bi] = p + bfc[0];
        }
    } else {
        #pragma unroll
        for (int bi = 0; bi < NB; bi++)
            out[BB + (size_t)BB * HH + (size_t)(b0 + bi) * HH + lane] =
                sh1[bi][0][lane];
    }
#undef PHASE
}

extern "C" void kernel_launch(void* const* d_in, const int* in_sizes, int n_in,
                              void* d_out, int out_size) {
    const float* x     = (const float*)d_in[0];
    const float* hs    = (const float*)d_in[1];
    const float* Wih0  = (const float*)d_in[2];
    const float* Whh0  = (const float*)d_in[3];
    const float* bih0  = (const float*)d_in[4];
    const float* bhh0  = (const float*)d_in[5];
    const float* Wih1  = (const float*)d_in[6];
    const float* Whh1  = (const float*)d_in[7];
    const float* bih1  = (const float*)d_in[8];
    const float* bhh1  = (const float*)d_in[9];
    const float* Wfc   = (const float*)d_in[10];
    const float* bfc   = (const float*)d_in[11];
    float* out = (float*)d_out;

    rnn2_kernel<<<BB / NB, 64>>>(x, hs, Wih0, Whh0, bih0, bhh0,
                                 Wih1, Whh1, bih1, bhh1, Wfc, bfc, out);
}

// round 14
// speedup vs baseline: 2.3709x; 2.3709x over previous
#include <cuda_runtime.h>

#define BB 4096
#define TT 512
#define HH 32

typedef unsigned long long u64;

__device__ __forceinline__ u64 pk2(float lo, float hi) {
    u64 r; asm("mov.b64 %0, {%1,%2};" : "=l"(r) : "f"(lo), "f"(hi)); return r;
}
__device__ __forceinline__ void unpk2(u64 v, float& a, float& b) {
    asm("mov.b64 {%0,%1}, %2;" : "=f"(a), "=f"(b) : "l"(v));
}
__device__ __forceinline__ u64 ffma2(u64 a, u64 b, u64 c) {
    u64 d; asm("fma.rn.f32x2 %0, %1, %2, %3;" : "=l"(d) : "l"(a), "l"(b), "l"(c));
    return d;
}
__device__ __forceinline__ u64 fadd2(u64 a, u64 b) {
    u64 d; asm("add.rn.f32x2 %0, %1, %2;" : "=l"(d) : "l"(a), "l"(b));
    return d;
}

// tanh with 2*log2(e) pre-folded: tanh(v) = 1 - 2*rcp(ex2(v') + 1)
__device__ __forceinline__ float tanh_scaled(float vp) {
    float e; asm("ex2.approx.f32 %0, %1;" : "=f"(e) : "f"(vp));
    float r; asm("rcp.approx.f32 %0, %1;" : "=f"(r) : "f"(e + 1.0f));
    return fmaf(-2.0f, r, 1.0f);
}

__global__ void __launch_bounds__(32)     // NO min-blocks clause: avoid the 128-reg clamp
rnn2_kernel(const float* __restrict__ x,       // [B, T, 1]
            const float* __restrict__ hstate,  // [2, B, H]
            const float* __restrict__ Wih0,    // [H, 1]
            const float* __restrict__ Whh0,    // [H, H]
            const float* __restrict__ bih0, const float* __restrict__ bhh0,
            const float* __restrict__ Wih1,    // [H, H]
            const float* __restrict__ Whh1,    // [H, H]
            const float* __restrict__ bih1, const float* __restrict__ bhh1,
            const float* __restrict__ Wfc,     // [1, H]
            const float* __restrict__ bfc,     // [1]
            float* __restrict__ out)           // [B] pred ++ [2,B,H] h_new
{
    // 128B rows; all lanes read the same 16B -> broadcast LDS.128.
    __shared__ __align__(16) float sh0[2][HH];   // [buf][neuron]
    __shared__ __align__(16) float sh1[2][HH];

    const int j = threadIdx.x;           // 0..31, one warp per block
    const int b = blockIdx.x;            // ONE batch per warp

    const float SC = 2.885390081777927f; // 2*log2(e), folded into weights

    // Weight rows for output neuron j, scaled, packed as f32x2 (k, k+1).
    u64 w0[16], wi1[16], wh1[16];
    {
        const float2* p = (const float2*)(Whh0 + j * HH);
        #pragma unroll
        for (int i = 0; i < 16; i++) { float2 f = p[i]; w0[i]  = pk2(f.x*SC, f.y*SC); }
        p = (const float2*)(Wih1 + j * HH);
        #pragma unroll
        for (int i = 0; i < 16; i++) { float2 f = p[i]; wi1[i] = pk2(f.x*SC, f.y*SC); }
        p = (const float2*)(Whh1 + j * HH);
        #pragma unroll
        for (int i = 0; i < 16; i++) { float2 f = p[i]; wh1[i] = pk2(f.x*SC, f.y*SC); }
    }
    const float wx0 = Wih0[j] * SC;
    const float bb0 = (bih0[j] + bhh0[j]) * SC;
    const float bb1 = (bih1[j] + bhh1[j]) * SC;

    sh0[0][j] = hstate[(size_t)b * HH + j];
    sh1[0][j] = hstate[(size_t)BB * HH + (size_t)b * HH + j];
    __syncwarp();

    const float* xb = x + (size_t)b * TT;

    // ---- prologue: L0(0): h0'(0) = tanh(Whh0@h0 + Wih0*x0 + b) -> buf 1 ----
    {
        u64 a  = pk2(fmaf(wx0, xb[0], bb0), 0.f);
        u64 ab = pk2(0.f, 0.f);
        const ulonglong2* hp = (const ulonglong2*)sh0[0];
        #pragma unroll
        for (int i = 0; i < 8; i++) {
            ulonglong2 v = hp[i];
            a  = ffma2(w0[2*i],     v.x, a);
            ab = ffma2(w0[2*i + 1], v.y, ab);
        }
        float lo, hi;
        unpk2(fadd2(a, ab), lo, hi);
        sh0[1][j] = tanh_scaled(lo + hi);
    }
    __syncwarp();

    float xv = xb[1];   // x for phase te=0 (consumed by L0(1))

    // ---- pipelined mainloop: phase t_e computes L0(t_e+1) and L1(t_e) ----
    // te runs 0..TT-1; the final phase's L0(TT) output lands in an unread
    // buffer (x clamped), its L1(TT-1) output is the real last state.
    #pragma unroll 1
    for (int t = 0; t < TT; t += 2) {
        #pragma unroll
        for (int s = 0; s < 2; s++) {     // t_e = t + s; compile-time parity
            const int rb0 = s ^ 1;        // h0'(t_e)
            const int wb0 = s;            // h0'(t_e+1)
            const int rb1 = s;            // h1'(t_e-1)
            const int wb1 = s ^ 1;        // h1'(t_e)

            int tn = t + s + 2; if (tn > TT - 1) tn = TT - 1;

            u64 a0  = pk2(fmaf(wx0, xv, bb0), 0.f);
            u64 a0b = pk2(0.f, 0.f);
            u64 a1  = pk2(bb1, 0.f);
            u64 a1b = pk2(0.f, 0.f);
            xv = xb[tn];

            // One LDS.128 of h0'(t_e) feeds BOTH Whh0 (L0) and Wih1 (L1)
            #pragma unroll
            for (int i = 0; i < 8; i++) {
                ulonglong2 v = ((const ulonglong2*)sh0[rb0])[i];
                a0  = ffma2(w0[2*i],      v.x, a0);
                a0b = ffma2(w0[2*i + 1],  v.y, a0b);
                a1  = ffma2(wi1[2*i],     v.x, a1);
                a1b = ffma2(wi1[2*i + 1], v.y, a1b);
            }
            // Whh1 @ h1'(t_e-1)
            #pragma unroll
            for (int i = 0; i < 8; i++) {
                ulonglong2 u = ((const ulonglong2*)sh1[rb1])[i];
                a1  = ffma2(wh1[2*i],     u.x, a1);
                a1b = ffma2(wh1[2*i + 1], u.y, a1b);
            }

            float lo, hi;
            unpk2(fadd2(a0, a0b), lo, hi);
            sh0[wb0][j] = tanh_scaled(lo + hi);   // h0'(t_e+1)
            unpk2(fadd2(a1, a1b), lo, hi);
            sh1[wb1][j] = tanh_scaled(lo + hi);   // h1'(t_e)
            __syncwarp();
        }
    }

    // ---- outputs ----
    // h0'(TT-1) is in sh0[0] (read buffer of the final phase);
    // h1'(TT-1) is in sh1[0] (write buffer of the final phase).
    const size_t ob = (size_t)b * HH + j;
    float h0l = sh0[0][j];
    float h1l = sh1[0][j];
    out[BB + ob]                   = h0l;    // h_new[0]
    out[BB + (size_t)BB * HH + ob] = h1l;    // h_new[1]

    float p = Wfc[j] * h1l;
    #pragma unroll
    for (int off = 16; off; off >>= 1)
        p += __shfl_xor_sync(0xffffffffu, p, off);
    if (j == 0) out[b] = p + bfc[0];
}

extern "C" void kernel_launch(void* const* d_in, const int* in_sizes, int n_in,
                              void* d_out, int out_size) {
    const float* x     = (const float*)d_in[0];
    const float* hs    = (const float*)d_in[1];
    const float* Wih0  = (const float*)d_in[2];
    const float* Whh0  = (const float*)d_in[3];
    const float* bih0  = (const float*)d_in[4];
    const float* bhh0  = (const float*)d_in[5];
    const float* Wih1  = (const float*)d_in[6];
    const float* Whh1  = (const float*)d_in[7];
    const float* bih1  = (const float*)d_in[8];
    const float* bhh1  = (const float*)d_in[9];
    const float* Wfc   = (const float*)d_in[10];
    const float* bfc   = (const float*)d_in[11];
    float* out = (float*)d_out;

    rnn2_kernel<<<BB, 32>>>(x, hs, Wih0, Whh0, bih0, bhh0,
                            Wih1, Whh1, bih1, bhh1, Wfc, bfc, out);
}